// round 10
// baseline (speedup 1.0000x reference)
#include <cuda_runtime.h>
#include <cuda_bf16.h>
#include <math.h>
#include <stdint.h>

#define NN 32768
#define KK 16

// ---------------- scratch (static device globals; no allocation) -------------
__device__ unsigned g_Pu1[NN * 128];    // layer1 gate preacts, bf16 pairs (256 cols)
__device__ unsigned g_Pu2[NN * 256];    // layer2 gate preacts, bf16 pairs (512 cols)
__device__ float g_HN1[NN * 64];        // layer1 LSTM output
__device__ float g_H1 [NN * 128];       // layer1 SAGE output
__device__ float g_HN2[NN * 128];       // layer2 LSTM output
__device__ float g_H2 [NN * 128];       // layer2 SAGE output
// packed bf16 weights (mma fragment order)
__device__ unsigned g_Wih1[64 * 256 / 2];
__device__ unsigned g_Wfs1[64 * 128 / 2];
__device__ unsigned g_Wfn1[64 * 128 / 2];
__device__ unsigned g_Whh1[64 * 256 / 2];
__device__ unsigned g_Wih2[128 * 512 / 2];
__device__ unsigned g_Wfs2[128 * 128 / 2];
__device__ unsigned g_Wfn2[128 * 128 / 2];
__device__ unsigned g_Whh2[128 * 512 / 2];

__device__ __forceinline__ float tanh_fast(float x) {
    float y;
    asm("tanh.approx.f32 %0, %1;" : "=f"(y) : "f"(x));
    return y;
}
__device__ __forceinline__ float sig_fast(float x) {
    return 0.5f * tanh_fast(0.5f * x) + 0.5f;
}

// -------- fused weight packing: all 8 matrices in ONE launch -----------------
struct PackArgs {
    const float* src[8];
    unsigned*    dst[8];
};
__constant__ int c_packK [8] = {64, 64, 64, 64, 128, 128, 128, 128};
__constant__ int c_packN [8] = {256, 128, 128, 256, 512, 128, 128, 512};
__constant__ int c_packIl[8] = {64, 0, 0, 64, 128, 0, 0, 128};
__constant__ int c_packOf[9] = {0, 8192, 12288, 16384, 24576, 57344, 65536, 73728, 106496};

__global__ void pack_all(PackArgs pa)
{
    int gidx = blockIdx.x * blockDim.x + threadIdx.x;
    if (gidx >= 106496) return;
    int s = 0;
    while (gidx >= c_packOf[s + 1]) s++;
    int idx = gidx - c_packOf[s];
    const int N = c_packN[s], ileaveD = c_packIl[s];
    const float* W = pa.src[s];

    int r    = idx & 1;
    int lane = (idx >> 1) & 31;
    int g8   = idx >> 6;
    int NT8  = N / 8;
    int k16  = g8 / NT8;
    int n8   = g8 % NT8;
    int k = k16 * 16 + (lane & 3) * 2 + r * 8;
    int n = n8 * 8 + (lane >> 2);
    int col = ileaveD ? (n & 3) * ileaveD + (n >> 2) : n;
    float e0 = W[(size_t)k * N + col];
    float e1 = W[(size_t)(k + 1) * N + col];
    __nv_bfloat162 p = __floats2bfloat162_rn(e0, e1);
    pa.dst[s][idx] = *(unsigned*)&p;
}

// -------- bf16 tensor-core fused GEMM ----------------------------------------
__global__ void __launch_bounds__(256) gemm_tc(
    const float* __restrict__ A0, int K0, const unsigned* __restrict__ Bp0,
    const float* __restrict__ A1, int K1, const unsigned* __restrict__ Bp1,
    const float* __restrict__ bias0, const float* __restrict__ bias1,
    float* __restrict__ Cf, unsigned* __restrict__ Cb,
    int Ntot, int act_sigmoid, int ileaveD)
{
    __shared__ __nv_bfloat16 As[128 * 136];

    const int tid  = threadIdx.x;
    const int lane = tid & 31;
    const int warp = tid >> 5;
    const int m0   = blockIdx.x * 128;
    const int nb0  = blockIdx.y * 16;      // n8 base
    const int NT8  = Ntot / 8;

    float acc[16][4];
#pragma unroll
    for (int nt = 0; nt < 16; nt++)
#pragma unroll
        for (int q = 0; q < 4; q++) acc[nt][q] = 0.0f;

    for (int pair = 0; pair < 2; pair++) {
        const float* A = pair ? A1 : A0;
        const unsigned* Bp = pair ? Bp1 : Bp0;
        const int K = pair ? K1 : K0;
        if (A == nullptr || K == 0) continue;
        const int KP = K + 8;
        const int K16 = K / 16;
        const int KC = K / 4;

        __syncthreads();
        for (int i = tid; i < 128 * KC; i += 256) {
            int row = i / KC, cc = i % KC;
            float4 v = *(const float4*)(A + (size_t)(m0 + row) * K + cc * 4);
            __nv_bfloat162 lo = __floats2bfloat162_rn(v.x, v.y);
            __nv_bfloat162 hi = __floats2bfloat162_rn(v.z, v.w);
            uint2 u = {*(unsigned*)&lo, *(unsigned*)&hi};
            *(uint2*)&As[row * KP + cc * 4] = u;
        }
        __syncthreads();

        const int arow  = warp * 16 + (lane & 15);
        const int acolb = (lane >> 4) << 3;
        for (int k16 = 0; k16 < K16; k16++) {
            unsigned a0, a1, a2, a3;
            unsigned addr =
                (unsigned)__cvta_generic_to_shared(&As[arow * KP + k16 * 16 + acolb]);
            asm volatile(
                "ldmatrix.sync.aligned.m8n8.x4.shared.b16 {%0,%1,%2,%3}, [%4];"
                : "=r"(a0), "=r"(a1), "=r"(a2), "=r"(a3) : "r"(addr));
#pragma unroll
            for (int nt = 0; nt < 16; nt++) {
                uint2 b = ((const uint2*)Bp)[(k16 * NT8 + nb0 + nt) * 32 + lane];
                asm volatile(
                    "mma.sync.aligned.m16n8k16.row.col.f32.bf16.bf16.f32 "
                    "{%0,%1,%2,%3},{%4,%5,%6,%7},{%8,%9},{%0,%1,%2,%3};"
                    : "+f"(acc[nt][0]), "+f"(acc[nt][1]), "+f"(acc[nt][2]), "+f"(acc[nt][3])
                    : "r"(a0), "r"(a1), "r"(a2), "r"(a3), "r"(b.x), "r"(b.y));
            }
        }
    }

    // epilogue
    const int r0 = m0 + warp * 16 + (lane >> 2);
    const int r1 = r0 + 8;
#pragma unroll
    for (int nt = 0; nt < 16; nt++) {
        int ci = (nb0 + nt) * 8 + 2 * (lane & 3);
        int lgA = ileaveD ? (ci & 3) * ileaveD + (ci >> 2) : ci;
        int cj = ci + 1;
        int lgB = ileaveD ? (cj & 3) * ileaveD + (cj >> 2) : cj;
        float bA = (bias0 ? bias0[lgA] : 0.0f) + (bias1 ? bias1[lgA] : 0.0f);
        float bB = (bias0 ? bias0[lgB] : 0.0f) + (bias1 ? bias1[lgB] : 0.0f);
        float v00 = acc[nt][0] + bA, v01 = acc[nt][1] + bB;
        float v10 = acc[nt][2] + bA, v11 = acc[nt][3] + bB;
        if (act_sigmoid) {
            v00 = 1.0f / (1.0f + __expf(-v00));
            v01 = 1.0f / (1.0f + __expf(-v01));
            v10 = 1.0f / (1.0f + __expf(-v10));
            v11 = 1.0f / (1.0f + __expf(-v11));
        }
        if (Cb) {
            __nv_bfloat162 p0 = __floats2bfloat162_rn(v00, v01);
            __nv_bfloat162 p1 = __floats2bfloat162_rn(v10, v11);
            Cb[(size_t)r0 * (Ntot / 2) + (ci >> 1)] = *(unsigned*)&p0;
            Cb[(size_t)r1 * (Ntot / 2) + (ci >> 1)] = *(unsigned*)&p1;
        } else {
            float2 f0 = {v00, v01}, f1 = {v10, v11};
            *(float2*)&Cf[(size_t)r0 * Ntot + ci] = f0;
            *(float2*)&Cf[(size_t)r1 * Ntot + ci] = f1;
        }
    }
}

// -------- persistent bf16 tensor-core LSTM, MC node-chunks per CTA -----------
// One CTA = MC*32 nodes processed as MC independent 32-node chunks per step
// (recurrence is row-wise, so chunks never interact). h double-buffered in
// smem (bf16); cell state in registers, balanced across lane pairs (even lane
// holds c(r0), odd lane holds c(r1)); full packed Whh in smem. ONE barrier per
// step; between barriers, MC chunk iterations of gather->mma->epi provide the
// ILP that hides ldmatrix/mma/MUFU/L2 latency.
template <int DIM, int WN, int NTHREADS, int MC>
__global__ void __launch_bounds__(NTHREADS, 1) lstm_persist(
    const unsigned* __restrict__ Pu,  // [NN][2*DIM] bf16 pairs (4*DIM cols)
    const unsigned* __restrict__ Bpk, // packed bf16 Whh
    const int*      __restrict__ nbr, // [NN][16]
    float*          __restrict__ HN)  // [NN][DIM] final h
{
    constexpr int C4     = 4 * DIM;
    constexpr int C2     = 2 * DIM;
    constexpr int K16    = DIM / 16;
    constexpr int NT8    = C4 / 8;
    constexpr int WC     = C4 / WN;
    constexpr int NTILES = WC / 8;
    constexpr int HP     = DIM + 8;
    constexpr int NODES  = 32 * MC;

    extern __shared__ unsigned smem_u[];
    unsigned*       Bsm = smem_u;                                   // DIM*C4/2 uints
    __nv_bfloat16*  Hs0 = (__nv_bfloat16*)(smem_u + DIM * C4 / 2);  // [NODES][HP]
    __nv_bfloat16*  Hs1 = Hs0 + NODES * HP;

    const int tid  = threadIdx.x;
    const int lane = tid & 31;
    const int warp = tid >> 5;
    const int wm   = warp / WN;     // 0..1 : 16-row slab within a chunk
    const int wn   = warp % WN;     // 0..WN-1 : WC-col slab
    const int base = blockIdx.x * NODES;

    // load packed B into smem (one time; reused all steps & chunks)
    for (int i = tid; i < DIM * C4 / 8; i += NTHREADS)
        ((uint4*)Bsm)[i] = ((const uint4*)Bpk)[i];

    float creg[MC][NTILES];
#pragma unroll
    for (int mc = 0; mc < MC; mc++)
#pragma unroll
        for (int nt = 0; nt < NTILES; nt++) creg[mc][nt] = 0.0f;

    const int  r0 = wm * 16 + (lane >> 2);   // row within chunk (0..31)
    const int  r1 = r0 + 8;
    const bool evenp = ((lane & 1) == 0);
    const int  arow  = wm * 16 + (lane & 15);
    const int  acolb = (lane >> 4) << 3;

    for (int t = 0; t < KK; t++) {
        __syncthreads();   // prev-step h writes (and initial B load) visible
        const __nv_bfloat16* Hr = (t & 1) ? Hs1 : Hs0;
        __nv_bfloat16*       Hw = (t & 1) ? Hs0 : Hs1;

#pragma unroll
        for (int mc = 0; mc < MC; mc++) {
            const int mcb = mc * 32;

            // ---- gather P (independent of h; overlaps this chunk's mma) ----
            const int j0 = __ldg(&nbr[(base + mcb + r0) * KK + t]);
            const int j1 = __ldg(&nbr[(base + mcb + r1) * KK + t]);
            unsigned pp0[NTILES], pp1[NTILES];
#pragma unroll
            for (int nt = 0; nt < NTILES; nt++) {
                int cu = ((wn * WC + nt * 8) >> 1) + (lane & 3);
                pp0[nt] = __ldg(&Pu[(size_t)j0 * C2 + cu]);
                pp1[nt] = __ldg(&Pu[(size_t)j1 * C2 + cu]);
            }

            // ---- mma -------------------------------------------------------
            float acc[NTILES][4];
#pragma unroll
            for (int nt = 0; nt < NTILES; nt++)
                acc[nt][0] = acc[nt][1] = acc[nt][2] = acc[nt][3] = 0.0f;

            if (t > 0) {
#pragma unroll
                for (int k16 = 0; k16 < K16; k16++) {
                    unsigned a0, a1, a2, a3;
                    unsigned addr = (unsigned)__cvta_generic_to_shared(
                        &Hr[(mcb + arow) * HP + k16 * 16 + acolb]);
                    asm volatile(
                        "ldmatrix.sync.aligned.m8n8.x4.shared.b16 {%0,%1,%2,%3}, [%4];"
                        : "=r"(a0), "=r"(a1), "=r"(a2), "=r"(a3) : "r"(addr));
#pragma unroll
                    for (int nt = 0; nt < NTILES; nt++) {
                        uint2 b = ((const uint2*)Bsm)[(k16 * NT8 + wn * NTILES + nt) * 32 + lane];
                        asm volatile(
                            "mma.sync.aligned.m16n8k16.row.col.f32.bf16.bf16.f32 "
                            "{%0,%1,%2,%3},{%4,%5,%6,%7},{%8,%9},{%0,%1,%2,%3};"
                            : "+f"(acc[nt][0]), "+f"(acc[nt][1]), "+f"(acc[nt][2]), "+f"(acc[nt][3])
                            : "r"(a0), "r"(a1), "r"(a2), "r"(a3), "r"(b.x), "r"(b.y));
                    }
                }
            }

            // ---- epilogue: balanced cell update ----------------------------
            // even lane holds c(r0,d); odd lane holds c(r1,d).
            // even lane cols = (i,f) of dim d; odd lane cols = (g,o).
#pragma unroll
            for (int nt = 0; nt < NTILES; nt++) {
                int ci = wn * WC + nt * 8 + 2 * (lane & 3);
                int d  = ci >> 2;
                float2 p0 = __bfloat1622float2(*(__nv_bfloat162*)&pp0[nt]);
                float2 p1 = __bfloat1622float2(*(__nv_bfloat162*)&pp1[nt]);
                float g00 = acc[nt][0] + p0.x;   // r0: even=i, odd=g
                float g01 = acc[nt][1] + p0.y;   // r0: even=f, odd=o
                float g10 = acc[nt][2] + p1.x;   // r1: even=i, odd=g
                float g11 = acc[nt][3] + p1.y;   // r1: even=f, odd=o
                float x00 = evenp ? sig_fast(g00) : tanh_fast(g00);  // si0 | tg0
                float x01 = sig_fast(g01);                           // sf0 | so0
                float x10 = evenp ? sig_fast(g10) : tanh_fast(g10);  // si1 | tg1
                float x11 = sig_fast(g11);                           // sf1 | so1
                // sa: even sends sf1(x11), odd sends tg0(x00)
                float sa = __shfl_xor_sync(0xffffffffu, evenp ? x11 : x00, 1);
                // sb: even sends si1(x10) -> odd receives si1
                float sb = __shfl_xor_sync(0xffffffffu, x10, 1);
                // even: c0' = sf0*c0 + si0*tg0 ; odd: c1' = sf1*c1 + si1*tg1
                float cn = evenp ? (x01 * creg[mc][nt] + x00 * sa)
                                 : (sa * creg[mc][nt] + sb * x10);
                creg[mc][nt] = cn;
                float tc = tanh_fast(cn);        // even: tanh(c0'); odd: tanh(c1')
                float sc = __shfl_xor_sync(0xffffffffu, tc, 1);  // odd gets tanh(c0')
                if (!evenp) {
                    float h0 = x01 * sc;         // so0 * tanh(c0')
                    float h1 = x11 * tc;         // so1 * tanh(c1')
                    Hw[(mcb + r0) * HP + d] = __float2bfloat16(h0);
                    Hw[(mcb + r1) * HP + d] = __float2bfloat16(h1);
                    if (t == KK - 1) {
                        HN[(size_t)(base + mcb + r0) * DIM + d] = h0;
                        HN[(size_t)(base + mcb + r1) * DIM + d] = h1;
                    }
                }
            }
        }
    }
}

// -------- per-graph readout + 2-layer head -----------------------------------
__global__ void __launch_bounds__(128) readout_kernel(
    const float* __restrict__ H2,
    const float* __restrict__ rwW, const float* __restrict__ rwb,
    const float* __restrict__ h1W, const float* __restrict__ h1b,
    const float* __restrict__ h2W, const float* __restrict__ h2b,
    float* __restrict__ out)
{
    const int g = blockIdx.x;
    const int t = threadIdx.x;
    __shared__ float h2s[32][128];
    __shared__ float wv[32];
    __shared__ float gembs[256];
    __shared__ float y1s[128];

    for (int idx = t; idx < 32 * 128; idx += 128)
        h2s[idx >> 7][idx & 127] = H2[(size_t)g * 32 * 128 + idx];
    __syncthreads();

    const int warp = t >> 5, lane = t & 31;
    float r0 = rwW[lane], r1 = rwW[lane + 32], r2 = rwW[lane + 64], r3 = rwW[lane + 96];
    for (int mm = 0; mm < 8; mm++) {
        int m = warp * 8 + mm;
        float s = h2s[m][lane] * r0 + h2s[m][lane + 32] * r1
                + h2s[m][lane + 64] * r2 + h2s[m][lane + 96] * r3;
#pragma unroll
        for (int o = 16; o; o >>= 1) s += __shfl_down_sync(0xffffffffu, s, o);
        if (lane == 0) wv[m] = 1.0f / (1.0f + __expf(-(s + rwb[0])));
    }
    __syncthreads();

    {
        float ws = 0.0f, mx = -INFINITY;
#pragma unroll
        for (int m = 0; m < 32; m++) {
            float v = h2s[m][t];
            ws += wv[m] * v;
            mx = fmaxf(mx, v);
        }
        gembs[t] = ws;
        gembs[128 + t] = mx;
    }
    __syncthreads();

    {
        float s = h1b[t];
        for (int cc = 0; cc < 256; cc++) s += gembs[cc] * h1W[cc * 128 + t];
        y1s[t] = 1.0f / (1.0f + __expf(-s));
    }
    __syncthreads();

    if (t < 2) {
        float s = h2b[t];
        for (int j = 0; j < 128; j++) s += y1s[j] * h2W[j * 2 + t];
        out[g * 2 + t] = 1.0f / (1.0f + __expf(-s));
    }
}

// ---------------------------- launch -----------------------------------------
extern "C" void kernel_launch(void* const* d_in, const int* in_sizes, int n_in,
                              void* d_out, int out_size)
{
    const float* xn    = (const float*)d_in[0];
    const int*   nbr   = (const int*)  d_in[1];
    const float* l1Wih = (const float*)d_in[4];
    const float* l1Whh = (const float*)d_in[5];
    const float* l1b   = (const float*)d_in[6];
    const float* fs1W  = (const float*)d_in[7];
    const float* fs1b  = (const float*)d_in[8];
    const float* fn1W  = (const float*)d_in[9];
    const float* fn1b  = (const float*)d_in[10];
    const float* l2Wih = (const float*)d_in[11];
    const float* l2Whh = (const float*)d_in[12];
    const float* l2b   = (const float*)d_in[13];
    const float* fs2W  = (const float*)d_in[14];
    const float* fs2b  = (const float*)d_in[15];
    const float* fn2W  = (const float*)d_in[16];
    const float* fn2b  = (const float*)d_in[17];
    const float* rwW   = (const float*)d_in[18];
    const float* rwb   = (const float*)d_in[19];
    const float* h1W   = (const float*)d_in[20];
    const float* h1b   = (const float*)d_in[21];
    const float* h2W   = (const float*)d_in[22];
    const float* h2b   = (const float*)d_in[23];
    float* out = (float*)d_out;

    unsigned *Pu1, *Pu2, *Wih1, *Wfs1, *Wfn1, *Whh1, *Wih2, *Wfs2, *Wfn2, *Whh2;
    float *HN1, *H1, *HN2, *H2;
    cudaGetSymbolAddress((void**)&Pu1,  g_Pu1);
    cudaGetSymbolAddress((void**)&Pu2,  g_Pu2);
    cudaGetSymbolAddress((void**)&HN1,  g_HN1);
    cudaGetSymbolAddress((void**)&H1,   g_H1);
    cudaGetSymbolAddress((void**)&HN2,  g_HN2);
    cudaGetSymbolAddress((void**)&H2,   g_H2);
    cudaGetSymbolAddress((void**)&Wih1, g_Wih1);
    cudaGetSymbolAddress((void**)&Wfs1, g_Wfs1);
    cudaGetSymbolAddress((void**)&Wfn1, g_Wfn1);
    cudaGetSymbolAddress((void**)&Whh1, g_Whh1);
    cudaGetSymbolAddress((void**)&Wih2, g_Wih2);
    cudaGetSymbolAddress((void**)&Wfs2, g_Wfs2);
    cudaGetSymbolAddress((void**)&Wfn2, g_Wfn2);
    cudaGetSymbolAddress((void**)&Whh2, g_Whh2);

    // smem: packed Whh + double-buffered h [2][128][DIM+8] bf16
    const int smem1 = 64 * 256 * 2 + 2 * 128 * (64 + 8) * 2;    //  69632 B
    const int smem2 = 128 * 512 * 2 + 2 * 128 * (128 + 8) * 2;  // 200704 B
    cudaFuncSetAttribute((const void*)lstm_persist<64, 16, 1024, 4>,
                         cudaFuncAttributeMaxDynamicSharedMemorySize, smem1);
    cudaFuncSetAttribute((const void*)lstm_persist<128, 8, 512, 4>,
                         cudaFuncAttributeMaxDynamicSharedMemorySize, smem2);

    // ---- pack all weights in ONE launch ------------------------------------
    PackArgs pa;
    pa.src[0] = l1Wih; pa.dst[0] = Wih1;
    pa.src[1] = fs1W;  pa.dst[1] = Wfs1;
    pa.src[2] = fn1W;  pa.dst[2] = Wfn1;
    pa.src[3] = l1Whh; pa.dst[3] = Whh1;
    pa.src[4] = l2Wih; pa.dst[4] = Wih2;
    pa.src[5] = fs2W;  pa.dst[5] = Wfs2;
    pa.src[6] = fn2W;  pa.dst[6] = Wfn2;
    pa.src[7] = l2Whh; pa.dst[7] = Whh2;
    pack_all<<<(106496 + 255) / 256, 256>>>(pa);

    // P1 = x @ Wih1 + b1  (gate-interleaved, bf16 pairs)
    gemm_tc<<<dim3(NN / 128, 2), 256>>>(
        xn, 64, Wih1, nullptr, 0, nullptr, l1b, nullptr,
        nullptr, Pu1, 256, 0, 64);

    // layer1 LSTM (persistent, 128 nodes/CTA, 4 chunks, 1024 threads)
    lstm_persist<64, 16, 1024, 4><<<NN / 128, 1024, smem1>>>(Pu1, Whh1, nbr, HN1);

    // H1 = sigmoid(x@Ws1 + HN1@Wn1 + bs1 + bn1)
    gemm_tc<<<dim3(NN / 128, 1), 256>>>(
        xn, 64, Wfs1, HN1, 64, Wfn1, fs1b, fn1b,
        H1, nullptr, 128, 1, 0);

    // P2 = H1 @ Wih2 + b2  (gate-interleaved, bf16 pairs)
    gemm_tc<<<dim3(NN / 128, 4), 256>>>(
        H1, 128, Wih2, nullptr, 0, nullptr, l2b, nullptr,
        nullptr, Pu2, 512, 0, 128);

    // layer2 LSTM (persistent, 128 nodes/CTA, 4 chunks, 512 threads)
    lstm_persist<128, 8, 512, 4><<<NN / 128, 512, smem2>>>(Pu2, Whh2, nbr, HN2);

    // H2 = sigmoid(H1@Ws2 + HN2@Wn2 + bs2 + bn2)
    gemm_tc<<<dim3(NN / 128, 1), 256>>>(
        H1, 128, Wfs2, HN2, 128, Wfn2, fs2b, fn2b,
        H2, nullptr, 128, 1, 0);

    // readout + head
    readout_kernel<<<1024, 128>>>(H2, rwW, rwb, h1W, h1b, h2W, h2b, out);
}

// round 13
// speedup vs baseline: 1.0643x; 1.0643x over previous
#include <cuda_runtime.h>
#include <cuda_bf16.h>
#include <math.h>
#include <stdint.h>

#define NN 32768
#define KK 16

// ---------------- scratch (static device globals; no allocation) -------------
__device__ unsigned g_Pu1[NN * 128];    // layer1 gate preacts, bf16 pairs (256 cols)
__device__ unsigned g_Pu2[NN * 256];    // layer2 gate preacts, bf16 pairs (512 cols)
__device__ float g_HN1[NN * 64];        // layer1 LSTM output
__device__ float g_H1 [NN * 128];       // layer1 SAGE output
__device__ float g_HN2[NN * 128];       // layer2 LSTM output
__device__ float g_H2 [NN * 128];       // layer2 SAGE output
// packed bf16 weights (mma fragment order)
__device__ unsigned g_Wih1[64 * 256 / 2];
__device__ unsigned g_Wfs1[64 * 128 / 2];
__device__ unsigned g_Wfn1[64 * 128 / 2];
__device__ unsigned g_Whh1[64 * 256 / 2];
__device__ unsigned g_Wih2[128 * 512 / 2];
__device__ unsigned g_Wfs2[128 * 128 / 2];
__device__ unsigned g_Wfn2[128 * 128 / 2];
__device__ unsigned g_Whh2[128 * 512 / 2];

__device__ __forceinline__ float tanh_fast(float x) {
    float y;
    asm("tanh.approx.f32 %0, %1;" : "=f"(y) : "f"(x));
    return y;
}
__device__ __forceinline__ float sig_fast(float x) {
    return 0.5f * tanh_fast(0.5f * x) + 0.5f;
}

// -------- fused weight packing: all 8 matrices in ONE launch -----------------
struct PackArgs {
    const float* src[8];
    unsigned*    dst[8];
};
__constant__ int c_packK [8] = {64, 64, 64, 64, 128, 128, 128, 128};
__constant__ int c_packN [8] = {256, 128, 128, 256, 512, 128, 128, 512};
__constant__ int c_packIl[8] = {64, 0, 0, 64, 128, 0, 0, 128};
__constant__ int c_packOf[9] = {0, 8192, 12288, 16384, 24576, 57344, 65536, 73728, 106496};

__global__ void pack_all(PackArgs pa)
{
    int gidx = blockIdx.x * blockDim.x + threadIdx.x;
    if (gidx >= 106496) return;
    int s = 0;
    while (gidx >= c_packOf[s + 1]) s++;
    int idx = gidx - c_packOf[s];
    const int N = c_packN[s], ileaveD = c_packIl[s];
    const float* W = pa.src[s];

    int r    = idx & 1;
    int lane = (idx >> 1) & 31;
    int g8   = idx >> 6;
    int NT8  = N / 8;
    int k16  = g8 / NT8;
    int n8   = g8 % NT8;
    int k = k16 * 16 + (lane & 3) * 2 + r * 8;
    int n = n8 * 8 + (lane >> 2);
    int col = ileaveD ? (n & 3) * ileaveD + (n >> 2) : n;
    float e0 = W[(size_t)k * N + col];
    float e1 = W[(size_t)(k + 1) * N + col];
    __nv_bfloat162 p = __floats2bfloat162_rn(e0, e1);
    pa.dst[s][idx] = *(unsigned*)&p;
}

// -------- bf16 tensor-core fused GEMM ----------------------------------------
__global__ void __launch_bounds__(256) gemm_tc(
    const float* __restrict__ A0, int K0, const unsigned* __restrict__ Bp0,
    const float* __restrict__ A1, int K1, const unsigned* __restrict__ Bp1,
    const float* __restrict__ bias0, const float* __restrict__ bias1,
    float* __restrict__ Cf, unsigned* __restrict__ Cb,
    int Ntot, int act_sigmoid, int ileaveD)
{
    __shared__ __nv_bfloat16 As[128 * 136];

    const int tid  = threadIdx.x;
    const int lane = tid & 31;
    const int warp = tid >> 5;
    const int m0   = blockIdx.x * 128;
    const int nb0  = blockIdx.y * 16;      // n8 base
    const int NT8  = Ntot / 8;

    float acc[16][4];
#pragma unroll
    for (int nt = 0; nt < 16; nt++)
#pragma unroll
        for (int q = 0; q < 4; q++) acc[nt][q] = 0.0f;

    for (int pair = 0; pair < 2; pair++) {
        const float* A = pair ? A1 : A0;
        const unsigned* Bp = pair ? Bp1 : Bp0;
        const int K = pair ? K1 : K0;
        if (A == nullptr || K == 0) continue;
        const int KP = K + 8;
        const int K16 = K / 16;
        const int KC = K / 4;

        __syncthreads();
        for (int i = tid; i < 128 * KC; i += 256) {
            int row = i / KC, cc = i % KC;
            float4 v = *(const float4*)(A + (size_t)(m0 + row) * K + cc * 4);
            __nv_bfloat162 lo = __floats2bfloat162_rn(v.x, v.y);
            __nv_bfloat162 hi = __floats2bfloat162_rn(v.z, v.w);
            uint2 u = {*(unsigned*)&lo, *(unsigned*)&hi};
            *(uint2*)&As[row * KP + cc * 4] = u;
        }
        __syncthreads();

        const int arow  = warp * 16 + (lane & 15);
        const int acolb = (lane >> 4) << 3;
        for (int k16 = 0; k16 < K16; k16++) {
            unsigned a0, a1, a2, a3;
            unsigned addr =
                (unsigned)__cvta_generic_to_shared(&As[arow * KP + k16 * 16 + acolb]);
            asm volatile(
                "ldmatrix.sync.aligned.m8n8.x4.shared.b16 {%0,%1,%2,%3}, [%4];"
                : "=r"(a0), "=r"(a1), "=r"(a2), "=r"(a3) : "r"(addr));
#pragma unroll
            for (int nt = 0; nt < 16; nt++) {
                uint2 b = ((const uint2*)Bp)[(k16 * NT8 + nb0 + nt) * 32 + lane];
                asm volatile(
                    "mma.sync.aligned.m16n8k16.row.col.f32.bf16.bf16.f32 "
                    "{%0,%1,%2,%3},{%4,%5,%6,%7},{%8,%9},{%0,%1,%2,%3};"
                    : "+f"(acc[nt][0]), "+f"(acc[nt][1]), "+f"(acc[nt][2]), "+f"(acc[nt][3])
                    : "r"(a0), "r"(a1), "r"(a2), "r"(a3), "r"(b.x), "r"(b.y));
            }
        }
    }

    // epilogue
    const int r0 = m0 + warp * 16 + (lane >> 2);
    const int r1 = r0 + 8;
#pragma unroll
    for (int nt = 0; nt < 16; nt++) {
        int ci = (nb0 + nt) * 8 + 2 * (lane & 3);
        int lgA = ileaveD ? (ci & 3) * ileaveD + (ci >> 2) : ci;
        int cj = ci + 1;
        int lgB = ileaveD ? (cj & 3) * ileaveD + (cj >> 2) : cj;
        float bA = (bias0 ? bias0[lgA] : 0.0f) + (bias1 ? bias1[lgA] : 0.0f);
        float bB = (bias0 ? bias0[lgB] : 0.0f) + (bias1 ? bias1[lgB] : 0.0f);
        float v00 = acc[nt][0] + bA, v01 = acc[nt][1] + bB;
        float v10 = acc[nt][2] + bA, v11 = acc[nt][3] + bB;
        if (act_sigmoid) {
            v00 = 1.0f / (1.0f + __expf(-v00));
            v01 = 1.0f / (1.0f + __expf(-v01));
            v10 = 1.0f / (1.0f + __expf(-v10));
            v11 = 1.0f / (1.0f + __expf(-v11));
        }
        if (Cb) {
            __nv_bfloat162 p0 = __floats2bfloat162_rn(v00, v01);
            __nv_bfloat162 p1 = __floats2bfloat162_rn(v10, v11);
            Cb[(size_t)r0 * (Ntot / 2) + (ci >> 1)] = *(unsigned*)&p0;
            Cb[(size_t)r1 * (Ntot / 2) + (ci >> 1)] = *(unsigned*)&p1;
        } else {
            float2 f0 = {v00, v01}, f1 = {v10, v11};
            *(float2*)&Cf[(size_t)r0 * Ntot + ci] = f0;
            *(float2*)&Cf[(size_t)r1 * Ntot + ci] = f1;
        }
    }
}

// -------- persistent bf16 tensor-core LSTM, MC node-chunks per CTA -----------
// One CTA = MC*32 nodes processed as MC independent 32-node chunks per step.
// h double-buffered in smem (bf16); cell state in registers, balanced across
// lane pairs; full packed Whh in smem. ONE barrier per step. Register budget
// is the hard constraint (Round-6/10 lesson): NTILES*4 (acc) + NTILES (creg*MC)
// + NTILES*2 (pp) must stay ~32 — thin warps (large WN), modest MC.
template <int DIM, int WN, int NTHREADS, int MC, int MINCTA>
__global__ void __launch_bounds__(NTHREADS, MINCTA) lstm_persist(
    const unsigned* __restrict__ Pu,  // [NN][2*DIM] bf16 pairs (4*DIM cols)
    const unsigned* __restrict__ Bpk, // packed bf16 Whh
    const int*      __restrict__ nbr, // [NN][16]
    float*          __restrict__ HN)  // [NN][DIM] final h
{
    constexpr int C4     = 4 * DIM;
    constexpr int C2     = 2 * DIM;
    constexpr int K16    = DIM / 16;
    constexpr int NT8    = C4 / 8;
    constexpr int WC     = C4 / WN;
    constexpr int NTILES = WC / 8;
    constexpr int HP     = DIM + 8;
    constexpr int NODES  = 32 * MC;

    extern __shared__ unsigned smem_u[];
    unsigned*       Bsm = smem_u;                                   // DIM*C4/2 uints
    __nv_bfloat16*  Hs0 = (__nv_bfloat16*)(smem_u + DIM * C4 / 2);  // [NODES][HP]
    __nv_bfloat16*  Hs1 = Hs0 + NODES * HP;

    const int tid  = threadIdx.x;
    const int lane = tid & 31;
    const int warp = tid >> 5;
    const int wm   = warp / WN;     // 0..1 : 16-row slab within a chunk
    const int wn   = warp % WN;     // 0..WN-1 : WC-col slab
    const int base = blockIdx.x * NODES;

    // load packed B into smem (one time; reused all steps & chunks)
    for (int i = tid; i < DIM * C4 / 8; i += NTHREADS)
        ((uint4*)Bsm)[i] = ((const uint4*)Bpk)[i];

    float creg[MC][NTILES];
#pragma unroll
    for (int mc = 0; mc < MC; mc++)
#pragma unroll
        for (int nt = 0; nt < NTILES; nt++) creg[mc][nt] = 0.0f;

    const int  r0 = wm * 16 + (lane >> 2);   // row within chunk (0..31)
    const int  r1 = r0 + 8;
    const bool evenp = ((lane & 1) == 0);
    const int  arow  = wm * 16 + (lane & 15);
    const int  acolb = (lane >> 4) << 3;

    for (int t = 0; t < KK; t++) {
        __syncthreads();   // prev-step h writes (and initial B load) visible
        const __nv_bfloat16* Hr = (t & 1) ? Hs1 : Hs0;
        __nv_bfloat16*       Hw = (t & 1) ? Hs0 : Hs1;

#pragma unroll
        for (int mc = 0; mc < MC; mc++) {
            const int mcb = mc * 32;

            // ---- gather P (independent of h; overlaps this chunk's mma) ----
            const int j0 = __ldg(&nbr[(base + mcb + r0) * KK + t]);
            const int j1 = __ldg(&nbr[(base + mcb + r1) * KK + t]);
            unsigned pp0[NTILES], pp1[NTILES];
#pragma unroll
            for (int nt = 0; nt < NTILES; nt++) {
                int cu = ((wn * WC + nt * 8) >> 1) + (lane & 3);
                pp0[nt] = __ldg(&Pu[(size_t)j0 * C2 + cu]);
                pp1[nt] = __ldg(&Pu[(size_t)j1 * C2 + cu]);
            }

            // ---- mma -------------------------------------------------------
            float acc[NTILES][4];
#pragma unroll
            for (int nt = 0; nt < NTILES; nt++)
                acc[nt][0] = acc[nt][1] = acc[nt][2] = acc[nt][3] = 0.0f;

            if (t > 0) {
#pragma unroll
                for (int k16 = 0; k16 < K16; k16++) {
                    unsigned a0, a1, a2, a3;
                    unsigned addr = (unsigned)__cvta_generic_to_shared(
                        &Hr[(mcb + arow) * HP + k16 * 16 + acolb]);
                    asm volatile(
                        "ldmatrix.sync.aligned.m8n8.x4.shared.b16 {%0,%1,%2,%3}, [%4];"
                        : "=r"(a0), "=r"(a1), "=r"(a2), "=r"(a3) : "r"(addr));
#pragma unroll
                    for (int nt = 0; nt < NTILES; nt++) {
                        uint2 b = ((const uint2*)Bsm)[(k16 * NT8 + wn * NTILES + nt) * 32 + lane];
                        asm volatile(
                            "mma.sync.aligned.m16n8k16.row.col.f32.bf16.bf16.f32 "
                            "{%0,%1,%2,%3},{%4,%5,%6,%7},{%8,%9},{%0,%1,%2,%3};"
                            : "+f"(acc[nt][0]), "+f"(acc[nt][1]), "+f"(acc[nt][2]), "+f"(acc[nt][3])
                            : "r"(a0), "r"(a1), "r"(a2), "r"(a3), "r"(b.x), "r"(b.y));
                    }
                }
            }

            // ---- epilogue: balanced cell update ----------------------------
            // even lane holds c(r0,d); odd lane holds c(r1,d).
#pragma unroll
            for (int nt = 0; nt < NTILES; nt++) {
                int ci = wn * WC + nt * 8 + 2 * (lane & 3);
                int d  = ci >> 2;
                float2 p0 = __bfloat1622float2(*(__nv_bfloat162*)&pp0[nt]);
                float2 p1 = __bfloat1622float2(*(__nv_bfloat162*)&pp1[nt]);
                float g00 = acc[nt][0] + p0.x;   // r0: even=i, odd=g
                float g01 = acc[nt][1] + p0.y;   // r0: even=f, odd=o
                float g10 = acc[nt][2] + p1.x;   // r1: even=i, odd=g
                float g11 = acc[nt][3] + p1.y;   // r1: even=f, odd=o
                float x00 = evenp ? sig_fast(g00) : tanh_fast(g00);  // si0 | tg0
                float x01 = sig_fast(g01);                           // sf0 | so0
                float x10 = evenp ? sig_fast(g10) : tanh_fast(g10);  // si1 | tg1
                float x11 = sig_fast(g11);                           // sf1 | so1
                float sa = __shfl_xor_sync(0xffffffffu, evenp ? x11 : x00, 1);
                float sb = __shfl_xor_sync(0xffffffffu, x10, 1);
                float cn = evenp ? (x01 * creg[mc][nt] + x00 * sa)
                                 : (sa * creg[mc][nt] + sb * x10);
                creg[mc][nt] = cn;
                float tc = tanh_fast(cn);
                float sc = __shfl_xor_sync(0xffffffffu, tc, 1);
                if (!evenp) {
                    float h0 = x01 * sc;
                    float h1 = x11 * tc;
                    Hw[(mcb + r0) * HP + d] = __float2bfloat16(h0);
                    Hw[(mcb + r1) * HP + d] = __float2bfloat16(h1);
                    if (t == KK - 1) {
                        HN[(size_t)(base + mcb + r0) * DIM + d] = h0;
                        HN[(size_t)(base + mcb + r1) * DIM + d] = h1;
                    }
                }
            }
        }
    }
}

// -------- per-graph readout + 2-layer head -----------------------------------
__global__ void __launch_bounds__(128) readout_kernel(
    const float* __restrict__ H2,
    const float* __restrict__ rwW, const float* __restrict__ rwb,
    const float* __restrict__ h1W, const float* __restrict__ h1b,
    const float* __restrict__ h2W, const float* __restrict__ h2b,
    float* __restrict__ out)
{
    const int g = blockIdx.x;
    const int t = threadIdx.x;
    __shared__ float h2s[32][128];
    __shared__ float wv[32];
    __shared__ float gembs[256];
    __shared__ float y1s[128];

    for (int idx = t; idx < 32 * 128; idx += 128)
        h2s[idx >> 7][idx & 127] = H2[(size_t)g * 32 * 128 + idx];
    __syncthreads();

    const int warp = t >> 5, lane = t & 31;
    float r0 = rwW[lane], r1 = rwW[lane + 32], r2 = rwW[lane + 64], r3 = rwW[lane + 96];
    for (int mm = 0; mm < 8; mm++) {
        int m = warp * 8 + mm;
        float s = h2s[m][lane] * r0 + h2s[m][lane + 32] * r1
                + h2s[m][lane + 64] * r2 + h2s[m][lane + 96] * r3;
#pragma unroll
        for (int o = 16; o; o >>= 1) s += __shfl_down_sync(0xffffffffu, s, o);
        if (lane == 0) wv[m] = 1.0f / (1.0f + __expf(-(s + rwb[0])));
    }
    __syncthreads();

    {
        float ws = 0.0f, mx = -INFINITY;
#pragma unroll
        for (int m = 0; m < 32; m++) {
            float v = h2s[m][t];
            ws += wv[m] * v;
            mx = fmaxf(mx, v);
        }
        gembs[t] = ws;
        gembs[128 + t] = mx;
    }
    __syncthreads();

    {
        float s = h1b[t];
        for (int cc = 0; cc < 256; cc++) s += gembs[cc] * h1W[cc * 128 + t];
        y1s[t] = 1.0f / (1.0f + __expf(-s));
    }
    __syncthreads();

    if (t < 2) {
        float s = h2b[t];
        for (int j = 0; j < 128; j++) s += y1s[j] * h2W[j * 2 + t];
        out[g * 2 + t] = 1.0f / (1.0f + __expf(-s));
    }
}

// ---------------------------- launch -----------------------------------------
extern "C" void kernel_launch(void* const* d_in, const int* in_sizes, int n_in,
                              void* d_out, int out_size)
{
    const float* xn    = (const float*)d_in[0];
    const int*   nbr   = (const int*)  d_in[1];
    const float* l1Wih = (const float*)d_in[4];
    const float* l1Whh = (const float*)d_in[5];
    const float* l1b   = (const float*)d_in[6];
    const float* fs1W  = (const float*)d_in[7];
    const float* fs1b  = (const float*)d_in[8];
    const float* fn1W  = (const float*)d_in[9];
    const float* fn1b  = (const float*)d_in[10];
    const float* l2Wih = (const float*)d_in[11];
    const float* l2Whh = (const float*)d_in[12];
    const float* l2b   = (const float*)d_in[13];
    const float* fs2W  = (const float*)d_in[14];
    const float* fs2b  = (const float*)d_in[15];
    const float* fn2W  = (const float*)d_in[16];
    const float* fn2b  = (const float*)d_in[17];
    const float* rwW   = (const float*)d_in[18];
    const float* rwb   = (const float*)d_in[19];
    const float* h1W   = (const float*)d_in[20];
    const float* h1b   = (const float*)d_in[21];
    const float* h2W   = (const float*)d_in[22];
    const float* h2b   = (const float*)d_in[23];
    float* out = (float*)d_out;

    unsigned *Pu1, *Pu2, *Wih1, *Wfs1, *Wfn1, *Whh1, *Wih2, *Wfs2, *Wfn2, *Whh2;
    float *HN1, *H1, *HN2, *H2;
    cudaGetSymbolAddress((void**)&Pu1,  g_Pu1);
    cudaGetSymbolAddress((void**)&Pu2,  g_Pu2);
    cudaGetSymbolAddress((void**)&HN1,  g_HN1);
    cudaGetSymbolAddress((void**)&H1,   g_H1);
    cudaGetSymbolAddress((void**)&HN2,  g_HN2);
    cudaGetSymbolAddress((void**)&H2,   g_H2);
    cudaGetSymbolAddress((void**)&Wih1, g_Wih1);
    cudaGetSymbolAddress((void**)&Wfs1, g_Wfs1);
    cudaGetSymbolAddress((void**)&Wfn1, g_Wfn1);
    cudaGetSymbolAddress((void**)&Whh1, g_Whh1);
    cudaGetSymbolAddress((void**)&Wih2, g_Wih2);
    cudaGetSymbolAddress((void**)&Wfs2, g_Wfs2);
    cudaGetSymbolAddress((void**)&Wfn2, g_Wfn2);
    cudaGetSymbolAddress((void**)&Whh2, g_Whh2);

    // layer1: 1024 thr, WN=16 (NTILES=2), MC=4 -> 128 nodes/CTA, grid 256,
    //         smem 69632 B, 2 CTA/SM -> single wave, ~16 live data regs.
    // layer2: 1024 thr, WN=16 (NTILES=4), MC=2 -> 64 nodes/CTA, grid 512,
    //         smem 165888 B, 1 CTA/SM -> 3.46 waves, ~32 live data regs.
    const int smem1 = 64 * 256 * 2 + 2 * 128 * (64 + 8) * 2;    //  69632 B
    const int smem2 = 128 * 512 * 2 + 2 * 64 * (128 + 8) * 2;   // 165888 B
    cudaFuncSetAttribute((const void*)lstm_persist<64, 16, 1024, 4, 2>,
                         cudaFuncAttributeMaxDynamicSharedMemorySize, smem1);
    cudaFuncSetAttribute((const void*)lstm_persist<128, 16, 1024, 2, 1>,
                         cudaFuncAttributeMaxDynamicSharedMemorySize, smem2);

    // ---- pack all weights in ONE launch ------------------------------------
    PackArgs pa;
    pa.src[0] = l1Wih; pa.dst[0] = Wih1;
    pa.src[1] = fs1W;  pa.dst[1] = Wfs1;
    pa.src[2] = fn1W;  pa.dst[2] = Wfn1;
    pa.src[3] = l1Whh; pa.dst[3] = Whh1;
    pa.src[4] = l2Wih; pa.dst[4] = Wih2;
    pa.src[5] = fs2W;  pa.dst[5] = Wfs2;
    pa.src[6] = fn2W;  pa.dst[6] = Wfn2;
    pa.src[7] = l2Whh; pa.dst[7] = Whh2;
    pack_all<<<(106496 + 255) / 256, 256>>>(pa);

    // P1 = x @ Wih1 + b1  (gate-interleaved, bf16 pairs)
    gemm_tc<<<dim3(NN / 128, 2), 256>>>(
        xn, 64, Wih1, nullptr, 0, nullptr, l1b, nullptr,
        nullptr, Pu1, 256, 0, 64);

    // layer1 LSTM
    lstm_persist<64, 16, 1024, 4, 2><<<NN / 128, 1024, smem1>>>(Pu1, Whh1, nbr, HN1);

    // H1 = sigmoid(x@Ws1 + HN1@Wn1 + bs1 + bn1)
    gemm_tc<<<dim3(NN / 128, 1), 256>>>(
        xn, 64, Wfs1, HN1, 64, Wfn1, fs1b, fn1b,
        H1, nullptr, 128, 1, 0);

    // P2 = H1 @ Wih2 + b2  (gate-interleaved, bf16 pairs)
    gemm_tc<<<dim3(NN / 128, 4), 256>>>(
        H1, 128, Wih2, nullptr, 0, nullptr, l2b, nullptr,
        nullptr, Pu2, 512, 0, 128);

    // layer2 LSTM
    lstm_persist<128, 16, 1024, 2, 1><<<NN / 64, 1024, smem2>>>(Pu2, Whh2, nbr, HN2);

    // H2 = sigmoid(H1@Ws2 + HN2@Wn2 + bs2 + bn2)
    gemm_tc<<<dim3(NN / 128, 1), 256>>>(
        H1, 128, Wfs2, HN2, 128, Wfn2, fs2b, fn2b,
        H2, nullptr, 128, 1, 0);

    // readout + head
    readout_kernel<<<1024, 128>>>(H2, rwW, rwb, h1W, h1b, h2W, h2b, out);
}

// round 14
// speedup vs baseline: 1.1807x; 1.1093x over previous
#include <cuda_runtime.h>
#include <cuda_bf16.h>
#include <math.h>
#include <stdint.h>

#define NN 32768
#define KK 16

// ---------------- scratch (static device globals; no allocation) -------------
__device__ unsigned g_Pu1[NN * 128];    // layer1 gate preacts, bf16 pairs (256 cols)
__device__ unsigned g_Pu2[NN * 256];    // layer2 gate preacts, bf16 pairs (512 cols)
__device__ float g_HN1[NN * 64];        // layer1 LSTM output
__device__ float g_H1 [NN * 128];       // layer1 SAGE output
__device__ float g_HN2[NN * 128];       // layer2 LSTM output
__device__ float g_H2 [NN * 128];       // layer2 SAGE output
// packed bf16 weights (mma fragment order)
__device__ unsigned g_Wih1[64 * 256 / 2];
__device__ unsigned g_Wfs1[64 * 128 / 2];
__device__ unsigned g_Wfn1[64 * 128 / 2];
__device__ unsigned g_Whh1[64 * 256 / 2];
__device__ unsigned g_Wih2[128 * 512 / 2];
__device__ unsigned g_Wfs2[128 * 128 / 2];
__device__ unsigned g_Wfn2[128 * 128 / 2];
__device__ unsigned g_Whh2[128 * 512 / 2];

__device__ __forceinline__ float tanh_fast(float x) {
    float y;
    asm("tanh.approx.f32 %0, %1;" : "=f"(y) : "f"(x));
    return y;
}
__device__ __forceinline__ float sig_fast(float x) {
    return 0.5f * tanh_fast(0.5f * x) + 0.5f;
}

// -------- fused weight packing: all 8 matrices in ONE launch -----------------
struct PackArgs {
    const float* src[8];
    unsigned*    dst[8];
};
__constant__ int c_packK [8] = {64, 64, 64, 64, 128, 128, 128, 128};
__constant__ int c_packN [8] = {256, 128, 128, 256, 512, 128, 128, 512};
__constant__ int c_packIl[8] = {64, 0, 0, 64, 128, 0, 0, 128};
__constant__ int c_packOf[9] = {0, 8192, 12288, 16384, 24576, 57344, 65536, 73728, 106496};

__global__ void pack_all(PackArgs pa)
{
    int gidx = blockIdx.x * blockDim.x + threadIdx.x;
    if (gidx >= 106496) return;
    int s = 0;
    while (gidx >= c_packOf[s + 1]) s++;
    int idx = gidx - c_packOf[s];
    const int N = c_packN[s], ileaveD = c_packIl[s];
    const float* W = pa.src[s];

    int r    = idx & 1;
    int lane = (idx >> 1) & 31;
    int g8   = idx >> 6;
    int NT8  = N / 8;
    int k16  = g8 / NT8;
    int n8   = g8 % NT8;
    int k = k16 * 16 + (lane & 3) * 2 + r * 8;
    int n = n8 * 8 + (lane >> 2);
    int col = ileaveD ? (n & 3) * ileaveD + (n >> 2) : n;
    float e0 = W[(size_t)k * N + col];
    float e1 = W[(size_t)(k + 1) * N + col];
    __nv_bfloat162 p = __floats2bfloat162_rn(e0, e1);
    pa.dst[s][idx] = *(unsigned*)&p;
}

// -------- bf16 tensor-core fused GEMM ----------------------------------------
__global__ void __launch_bounds__(256, 2) gemm_tc(
    const float* __restrict__ A0, int K0, const unsigned* __restrict__ Bp0,
    const float* __restrict__ A1, int K1, const unsigned* __restrict__ Bp1,
    const float* __restrict__ bias0, const float* __restrict__ bias1,
    float* __restrict__ Cf, unsigned* __restrict__ Cb,
    int Ntot, int act_sigmoid, int ileaveD)
{
    __shared__ __nv_bfloat16 As[128 * 136];

    const int tid  = threadIdx.x;
    const int lane = tid & 31;
    const int warp = tid >> 5;
    const int m0   = blockIdx.x * 128;
    const int nb0  = blockIdx.y * 16;      // n8 base
    const int NT8  = Ntot / 8;

    float acc[16][4];
#pragma unroll
    for (int nt = 0; nt < 16; nt++)
#pragma unroll
        for (int q = 0; q < 4; q++) acc[nt][q] = 0.0f;

    for (int pair = 0; pair < 2; pair++) {
        const float* A = pair ? A1 : A0;
        const unsigned* Bp = pair ? Bp1 : Bp0;
        const int K = pair ? K1 : K0;
        if (A == nullptr || K == 0) continue;
        const int KP = K + 8;
        const int K16 = K / 16;
        const int KC = K / 4;

        __syncthreads();
        for (int i = tid; i < 128 * KC; i += 256) {
            int row = i / KC, cc = i % KC;
            float4 v = *(const float4*)(A + (size_t)(m0 + row) * K + cc * 4);
            __nv_bfloat162 lo = __floats2bfloat162_rn(v.x, v.y);
            __nv_bfloat162 hi = __floats2bfloat162_rn(v.z, v.w);
            uint2 u = {*(unsigned*)&lo, *(unsigned*)&hi};
            *(uint2*)&As[row * KP + cc * 4] = u;
        }
        __syncthreads();

        const int arow  = warp * 16 + (lane & 15);
        const int acolb = (lane >> 4) << 3;
        for (int k16 = 0; k16 < K16; k16++) {
            unsigned a0, a1, a2, a3;
            unsigned addr =
                (unsigned)__cvta_generic_to_shared(&As[arow * KP + k16 * 16 + acolb]);
            asm volatile(
                "ldmatrix.sync.aligned.m8n8.x4.shared.b16 {%0,%1,%2,%3}, [%4];"
                : "=r"(a0), "=r"(a1), "=r"(a2), "=r"(a3) : "r"(addr));
#pragma unroll
            for (int nt = 0; nt < 16; nt++) {
                uint2 b = ((const uint2*)Bp)[(k16 * NT8 + nb0 + nt) * 32 + lane];
                asm volatile(
                    "mma.sync.aligned.m16n8k16.row.col.f32.bf16.bf16.f32 "
                    "{%0,%1,%2,%3},{%4,%5,%6,%7},{%8,%9},{%0,%1,%2,%3};"
                    : "+f"(acc[nt][0]), "+f"(acc[nt][1]), "+f"(acc[nt][2]), "+f"(acc[nt][3])
                    : "r"(a0), "r"(a1), "r"(a2), "r"(a3), "r"(b.x), "r"(b.y));
            }
        }
    }

    // epilogue
    const int r0 = m0 + warp * 16 + (lane >> 2);
    const int r1 = r0 + 8;
#pragma unroll
    for (int nt = 0; nt < 16; nt++) {
        int ci = (nb0 + nt) * 8 + 2 * (lane & 3);
        int lgA = ileaveD ? (ci & 3) * ileaveD + (ci >> 2) : ci;
        int cj = ci + 1;
        int lgB = ileaveD ? (cj & 3) * ileaveD + (cj >> 2) : cj;
        float bA = (bias0 ? bias0[lgA] : 0.0f) + (bias1 ? bias1[lgA] : 0.0f);
        float bB = (bias0 ? bias0[lgB] : 0.0f) + (bias1 ? bias1[lgB] : 0.0f);
        float v00 = acc[nt][0] + bA, v01 = acc[nt][1] + bB;
        float v10 = acc[nt][2] + bA, v11 = acc[nt][3] + bB;
        if (act_sigmoid) {
            v00 = 1.0f / (1.0f + __expf(-v00));
            v01 = 1.0f / (1.0f + __expf(-v01));
            v10 = 1.0f / (1.0f + __expf(-v10));
            v11 = 1.0f / (1.0f + __expf(-v11));
        }
        if (Cb) {
            __nv_bfloat162 p0 = __floats2bfloat162_rn(v00, v01);
            __nv_bfloat162 p1 = __floats2bfloat162_rn(v10, v11);
            Cb[(size_t)r0 * (Ntot / 2) + (ci >> 1)] = *(unsigned*)&p0;
            Cb[(size_t)r1 * (Ntot / 2) + (ci >> 1)] = *(unsigned*)&p1;
        } else {
            float2 f0 = {v00, v01}, f1 = {v10, v11};
            *(float2*)&Cf[(size_t)r0 * Ntot + ci] = f0;
            *(float2*)&Cf[(size_t)r1 * Ntot + ci] = f1;
        }
    }
}

// -------- persistent bf16 tensor-core LSTM -----------------------------------
// One CTA = 32 nodes. h double-buffered in smem (bf16); c in registers; full
// packed Whh in smem. Software-pipelined gather: the step-(t+1) nbr indices
// (and for PREF_DATA=1, the full P data) are prefetched at the END of step t,
// before the barrier, so their L2 latency overlaps barrier-wait + next mma
// instead of sitting on the serial critical path.
template <int DIM, int WN, int NTHREADS, int MINCTA, int PREF_DATA>
__global__ void __launch_bounds__(NTHREADS, MINCTA) lstm_persist(
    const unsigned* __restrict__ Pu,  // [NN][2*DIM] bf16 pairs (4*DIM cols)
    const unsigned* __restrict__ Bpk, // packed bf16 Whh
    const int*      __restrict__ nbr, // [NN][16]
    float*          __restrict__ HN)  // [NN][DIM] final h
{
    constexpr int C4     = 4 * DIM;
    constexpr int C2     = 2 * DIM;
    constexpr int K16    = DIM / 16;
    constexpr int NT8    = C4 / 8;
    constexpr int WC     = C4 / WN;
    constexpr int NTILES = WC / 8;
    constexpr int HP     = DIM + 8;

    extern __shared__ unsigned smem_u[];
    unsigned*       Bsm = smem_u;                                   // DIM*C4/2 uints
    __nv_bfloat16*  Hs0 = (__nv_bfloat16*)(smem_u + DIM * C4 / 2);  // [32][HP]
    __nv_bfloat16*  Hs1 = Hs0 + 32 * HP;

    const int tid  = threadIdx.x;
    const int lane = tid & 31;
    const int warp = tid >> 5;
    const int wm   = warp / WN;     // 0..1 : 16-row slab
    const int wn   = warp % WN;     // 0..WN-1 : WC-col slab
    const int base = blockIdx.x * 32;

    // load packed B into smem (one time; reused all 16 steps)
    for (int i = tid; i < DIM * C4 / 8; i += NTHREADS)
        ((uint4*)Bsm)[i] = ((const uint4*)Bpk)[i];
    __syncthreads();

    float creg[NTILES][2];
#pragma unroll
    for (int nt = 0; nt < NTILES; nt++) { creg[nt][0] = 0.0f; creg[nt][1] = 0.0f; }

    const int  r0 = wm * 16 + (lane >> 2);
    const int  r1 = r0 + 8;
    const bool evenp = ((lane & 1) == 0);
    const int  arow  = wm * 16 + (lane & 15);
    const int  acolb = (lane >> 4) << 3;
    const int  cu0   = ((wn * WC) >> 1) + (lane & 3);

    // ---- prologue: prefetch step-0 indices (and data if PREF_DATA) ---------
    int jn0 = __ldg(&nbr[(base + r0) * KK + 0]);
    int jn1 = __ldg(&nbr[(base + r1) * KK + 0]);
    unsigned ppn0[PREF_DATA ? NTILES : 1], ppn1[PREF_DATA ? NTILES : 1];
    if (PREF_DATA) {
#pragma unroll
        for (int nt = 0; nt < NTILES; nt++) {
            ppn0[nt] = __ldg(&Pu[(size_t)jn0 * C2 + cu0 + nt * 4]);
            ppn1[nt] = __ldg(&Pu[(size_t)jn1 * C2 + cu0 + nt * 4]);
        }
    }

    for (int t = 0; t < KK; t++) {
        // ---- consume prefetched indices; gather data (if not prefetched) ---
        const int j0 = jn0, j1 = jn1;
        unsigned pp0[NTILES], pp1[NTILES];
        if (PREF_DATA) {
#pragma unroll
            for (int nt = 0; nt < NTILES; nt++) { pp0[nt] = ppn0[nt]; pp1[nt] = ppn1[nt]; }
        } else {
#pragma unroll
            for (int nt = 0; nt < NTILES; nt++) {
                pp0[nt] = __ldg(&Pu[(size_t)j0 * C2 + cu0 + nt * 4]);
                pp1[nt] = __ldg(&Pu[(size_t)j1 * C2 + cu0 + nt * 4]);
            }
        }

        __syncthreads();   // h_{t-1} writes (prev epilogue) now visible

        float acc[NTILES][4];
#pragma unroll
        for (int nt = 0; nt < NTILES; nt++)
            acc[nt][0] = acc[nt][1] = acc[nt][2] = acc[nt][3] = 0.0f;

        if (t > 0) {
            const __nv_bfloat16* Hr = (t & 1) ? Hs1 : Hs0;
#pragma unroll
            for (int k16 = 0; k16 < K16; k16++) {
                unsigned a0, a1, a2, a3;
                unsigned addr =
                    (unsigned)__cvta_generic_to_shared(&Hr[arow * HP + k16 * 16 + acolb]);
                asm volatile(
                    "ldmatrix.sync.aligned.m8n8.x4.shared.b16 {%0,%1,%2,%3}, [%4];"
                    : "=r"(a0), "=r"(a1), "=r"(a2), "=r"(a3) : "r"(addr));
#pragma unroll
                for (int nt = 0; nt < NTILES; nt++) {
                    uint2 b = ((const uint2*)Bsm)[(k16 * NT8 + wn * NTILES + nt) * 32 + lane];
                    asm volatile(
                        "mma.sync.aligned.m16n8k16.row.col.f32.bf16.bf16.f32 "
                        "{%0,%1,%2,%3},{%4,%5,%6,%7},{%8,%9},{%0,%1,%2,%3};"
                        : "+f"(acc[nt][0]), "+f"(acc[nt][1]), "+f"(acc[nt][2]), "+f"(acc[nt][3])
                        : "r"(a0), "r"(a1), "r"(a2), "r"(a3), "r"(b.x), "r"(b.y));
                }
            }
        }

        // ---- prefetch step t+1: indices first, then (optionally) data ------
        if (t + 1 < KK) {
            jn0 = __ldg(&nbr[(base + r0) * KK + t + 1]);
            jn1 = __ldg(&nbr[(base + r1) * KK + t + 1]);
            if (PREF_DATA) {
#pragma unroll
                for (int nt = 0; nt < NTILES; nt++) {
                    ppn0[nt] = __ldg(&Pu[(size_t)jn0 * C2 + cu0 + nt * 4]);
                    ppn1[nt] = __ldg(&Pu[(size_t)jn1 * C2 + cu0 + nt * 4]);
                }
            }
        }

        // ---- epilogue: cell update; writes go to the OTHER h buffer --------
        __nv_bfloat16* Hw = (t & 1) ? Hs0 : Hs1;
#pragma unroll
        for (int nt = 0; nt < NTILES; nt++) {
            int ci = wn * WC + nt * 8 + 2 * (lane & 3);
            int d  = ci >> 2;
            float2 p0 = __bfloat1622float2(*(__nv_bfloat162*)&pp0[nt]);
            float2 p1 = __bfloat1622float2(*(__nv_bfloat162*)&pp1[nt]);
            float g00 = acc[nt][0] + p0.x;   // even lane: i | odd lane: g
            float g01 = acc[nt][1] + p0.y;   // even lane: f | odd lane: o
            float g10 = acc[nt][2] + p1.x;
            float g11 = acc[nt][3] + p1.y;
            float x00 = evenp ? sig_fast(g00) : tanh_fast(g00);
            float x01 = sig_fast(g01);
            float x10 = evenp ? sig_fast(g10) : tanh_fast(g10);
            float x11 = sig_fast(g11);
            float y00 = __shfl_xor_sync(0xffffffffu, x00, 1);  // even view: tanh(g)
            float y10 = __shfl_xor_sync(0xffffffffu, x10, 1);
            float cn0 = x01 * creg[nt][0] + x00 * y00;         // even: sf*c + si*tg
            float cn1 = x11 * creg[nt][1] + x10 * y10;
            float tc0 = tanh_fast(cn0);
            float tc1 = tanh_fast(cn1);
            float tz0 = __shfl_xor_sync(0xffffffffu, tc0, 1);  // odd view: tanh(c)
            float tz1 = __shfl_xor_sync(0xffffffffu, tc1, 1);
            if (evenp) {
                creg[nt][0] = cn0;
                creg[nt][1] = cn1;
            } else {
                float h0 = x01 * tz0;                          // so * tanh(c)
                float h1 = x11 * tz1;
                Hw[r0 * HP + d] = __float2bfloat16(h0);
                Hw[r1 * HP + d] = __float2bfloat16(h1);
                if (t == KK - 1) {
                    HN[(size_t)(base + r0) * DIM + d] = h0;
                    HN[(size_t)(base + r1) * DIM + d] = h1;
                }
            }
        }
    }
}

// -------- per-graph readout + 2-layer head -----------------------------------
__global__ void __launch_bounds__(128) readout_kernel(
    const float* __restrict__ H2,
    const float* __restrict__ rwW, const float* __restrict__ rwb,
    const float* __restrict__ h1W, const float* __restrict__ h1b,
    const float* __restrict__ h2W, const float* __restrict__ h2b,
    float* __restrict__ out)
{
    const int g = blockIdx.x;
    const int t = threadIdx.x;
    __shared__ float h2s[32][128];
    __shared__ float wv[32];
    __shared__ float gembs[256];
    __shared__ float y1s[128];

    for (int idx = t; idx < 32 * 128; idx += 128)
        h2s[idx >> 7][idx & 127] = H2[(size_t)g * 32 * 128 + idx];
    __syncthreads();

    const int warp = t >> 5, lane = t & 31;
    float r0 = rwW[lane], r1 = rwW[lane + 32], r2 = rwW[lane + 64], r3 = rwW[lane + 96];
    for (int mm = 0; mm < 8; mm++) {
        int m = warp * 8 + mm;
        float s = h2s[m][lane] * r0 + h2s[m][lane + 32] * r1
                + h2s[m][lane + 64] * r2 + h2s[m][lane + 96] * r3;
#pragma unroll
        for (int o = 16; o; o >>= 1) s += __shfl_down_sync(0xffffffffu, s, o);
        if (lane == 0) wv[m] = 1.0f / (1.0f + __expf(-(s + rwb[0])));
    }
    __syncthreads();

    {
        float ws = 0.0f, mx = -INFINITY;
#pragma unroll
        for (int m = 0; m < 32; m++) {
            float v = h2s[m][t];
            ws += wv[m] * v;
            mx = fmaxf(mx, v);
        }
        gembs[t] = ws;
        gembs[128 + t] = mx;
    }
    __syncthreads();

    {
        float s = h1b[t];
        for (int cc = 0; cc < 256; cc++) s += gembs[cc] * h1W[cc * 128 + t];
        y1s[t] = 1.0f / (1.0f + __expf(-s));
    }
    __syncthreads();

    if (t < 2) {
        float s = h2b[t];
        for (int j = 0; j < 128; j++) s += y1s[j] * h2W[j * 2 + t];
        out[g * 2 + t] = 1.0f / (1.0f + __expf(-s));
    }
}

// ---------------------------- launch -----------------------------------------
extern "C" void kernel_launch(void* const* d_in, const int* in_sizes, int n_in,
                              void* d_out, int out_size)
{
    const float* xn    = (const float*)d_in[0];
    const int*   nbr   = (const int*)  d_in[1];
    const float* l1Wih = (const float*)d_in[4];
    const float* l1Whh = (const float*)d_in[5];
    const float* l1b   = (const float*)d_in[6];
    const float* fs1W  = (const float*)d_in[7];
    const float* fs1b  = (const float*)d_in[8];
    const float* fn1W  = (const float*)d_in[9];
    const float* fn1b  = (const float*)d_in[10];
    const float* l2Wih = (const float*)d_in[11];
    const float* l2Whh = (const float*)d_in[12];
    const float* l2b   = (const float*)d_in[13];
    const float* fs2W  = (const float*)d_in[14];
    const float* fs2b  = (const float*)d_in[15];
    const float* fn2W  = (const float*)d_in[16];
    const float* fn2b  = (const float*)d_in[17];
    const float* rwW   = (const float*)d_in[18];
    const float* rwb   = (const float*)d_in[19];
    const float* h1W   = (const float*)d_in[20];
    const float* h1b   = (const float*)d_in[21];
    const float* h2W   = (const float*)d_in[22];
    const float* h2b   = (const float*)d_in[23];
    float* out = (float*)d_out;

    unsigned *Pu1, *Pu2, *Wih1, *Wfs1, *Wfn1, *Whh1, *Wih2, *Wfs2, *Wfn2, *Whh2;
    float *HN1, *H1, *HN2, *H2;
    cudaGetSymbolAddress((void**)&Pu1,  g_Pu1);
    cudaGetSymbolAddress((void**)&Pu2,  g_Pu2);
    cudaGetSymbolAddress((void**)&HN1,  g_HN1);
    cudaGetSymbolAddress((void**)&H1,   g_H1);
    cudaGetSymbolAddress((void**)&HN2,  g_HN2);
    cudaGetSymbolAddress((void**)&H2,   g_H2);
    cudaGetSymbolAddress((void**)&Wih1, g_Wih1);
    cudaGetSymbolAddress((void**)&Wfs1, g_Wfs1);
    cudaGetSymbolAddress((void**)&Wfn1, g_Wfn1);
    cudaGetSymbolAddress((void**)&Whh1, g_Whh1);
    cudaGetSymbolAddress((void**)&Wih2, g_Wih2);
    cudaGetSymbolAddress((void**)&Wfs2, g_Wfs2);
    cudaGetSymbolAddress((void**)&Wfn2, g_Wfn2);
    cudaGetSymbolAddress((void**)&Whh2, g_Whh2);

    // smem: packed Whh + double-buffered h [2][32][DIM+8] bf16  (Round-8 geom)
    const int smem1 = 64 * 256 * 2 + 2 * 32 * (64 + 8) * 2;     //  41984 B
    const int smem2 = 128 * 512 * 2 + 2 * 32 * (128 + 8) * 2;   // 148480 B
    cudaFuncSetAttribute((const void*)lstm_persist<64, 8, 512, 2, 1>,
                         cudaFuncAttributeMaxDynamicSharedMemorySize, smem1);
    cudaFuncSetAttribute((const void*)lstm_persist<128, 16, 1024, 1, 0>,
                         cudaFuncAttributeMaxDynamicSharedMemorySize, smem2);

    // ---- pack all weights in ONE launch ------------------------------------
    PackArgs pa;
    pa.src[0] = l1Wih; pa.dst[0] = Wih1;
    pa.src[1] = fs1W;  pa.dst[1] = Wfs1;
    pa.src[2] = fn1W;  pa.dst[2] = Wfn1;
    pa.src[3] = l1Whh; pa.dst[3] = Whh1;
    pa.src[4] = l2Wih; pa.dst[4] = Wih2;
    pa.src[5] = fs2W;  pa.dst[5] = Wfs2;
    pa.src[6] = fn2W;  pa.dst[6] = Wfn2;
    pa.src[7] = l2Whh; pa.dst[7] = Whh2;
    pack_all<<<(106496 + 255) / 256, 256>>>(pa);

    // P1 = x @ Wih1 + b1  (gate-interleaved, bf16 pairs)
    gemm_tc<<<dim3(NN / 128, 2), 256>>>(
        xn, 64, Wih1, nullptr, 0, nullptr, l1b, nullptr,
        nullptr, Pu1, 256, 0, 64);

    // layer1 LSTM (512 thr, 2 CTA/SM, full data prefetch across the barrier)
    lstm_persist<64, 8, 512, 2, 1><<<NN / 32, 512, smem1>>>(Pu1, Whh1, nbr, HN1);

    // H1 = sigmoid(x@Ws1 + HN1@Wn1 + bs1 + bn1)
    gemm_tc<<<dim3(NN / 128, 1), 256>>>(
        xn, 64, Wfs1, HN1, 64, Wfn1, fs1b, fn1b,
        H1, nullptr, 128, 1, 0);

    // P2 = H1 @ Wih2 + b2  (gate-interleaved, bf16 pairs)
    gemm_tc<<<dim3(NN / 128, 4), 256>>>(
        H1, 128, Wih2, nullptr, 0, nullptr, l2b, nullptr,
        nullptr, Pu2, 512, 0, 128);

    // layer2 LSTM (1024 thr; index-only prefetch — register budget is 64/thr)
    lstm_persist<128, 16, 1024, 1, 0><<<NN / 32, 1024, smem2>>>(Pu2, Whh2, nbr, HN2);

    // H2 = sigmoid(H1@Ws2 + HN2@Wn2 + bs2 + bn2)
    gemm_tc<<<dim3(NN / 128, 1), 256>>>(
        H1, 128, Wfs2, HN2, 128, Wfn2, fs2b, fn2b,
        H2, nullptr, 128, 1, 0);

    // readout + head
    readout_kernel<<<1024, 128>>>(H2, rwW, rwb, h1W, h1b, h2W, h2b, out);
}

// round 15
// speedup vs baseline: 1.3017x; 1.1025x over previous
#include <cuda_runtime.h>
#include <cuda_bf16.h>
#include <math.h>
#include <stdint.h>

#define NN 32768
#define KK 16

// ---------------- scratch (static device globals; no allocation) -------------
__device__ unsigned g_Pu1[NN * 128];    // layer1 gate preacts, bf16 pairs (256 cols)
__device__ unsigned g_Pu2[NN * 256];    // layer2 gate preacts, bf16 pairs (512 cols)
__device__ float g_HN1[NN * 64];        // layer1 LSTM output
__device__ float g_H1 [NN * 128];       // layer1 SAGE output
__device__ float g_HN2[NN * 128];       // layer2 LSTM output
__device__ float g_H2 [NN * 128];       // layer2 SAGE output
// packed bf16 weights (mma fragment order)
__device__ unsigned g_Wih1[64 * 256 / 2];
__device__ unsigned g_Wfs1[64 * 128 / 2];
__device__ unsigned g_Wfn1[64 * 128 / 2];
__device__ unsigned g_Whh1[64 * 256 / 2];
__device__ unsigned g_Wih2[128 * 512 / 2];
__device__ unsigned g_Wfs2[128 * 128 / 2];
__device__ unsigned g_Wfn2[128 * 128 / 2];
__device__ unsigned g_Whh2[128 * 512 / 2];

__device__ __forceinline__ float tanh_fast(float x) {
    float y;
    asm("tanh.approx.f32 %0, %1;" : "=f"(y) : "f"(x));
    return y;
}
__device__ __forceinline__ float sig_fast(float x) {
    return 0.5f * tanh_fast(0.5f * x) + 0.5f;
}

// -------- fused weight packing: all 8 matrices in ONE launch -----------------
struct PackArgs {
    const float* src[8];
    unsigned*    dst[8];
};
__constant__ int c_packK [8] = {64, 64, 64, 64, 128, 128, 128, 128};
__constant__ int c_packN [8] = {256, 128, 128, 256, 512, 128, 128, 512};
__constant__ int c_packIl[8] = {64, 0, 0, 64, 128, 0, 0, 128};
__constant__ int c_packOf[9] = {0, 8192, 12288, 16384, 24576, 57344, 65536, 73728, 106496};

__global__ void pack_all(PackArgs pa)
{
    int gidx = blockIdx.x * blockDim.x + threadIdx.x;
    if (gidx >= 106496) return;
    int s = 0;
    while (gidx >= c_packOf[s + 1]) s++;
    int idx = gidx - c_packOf[s];
    const int N = c_packN[s], ileaveD = c_packIl[s];
    const float* W = pa.src[s];

    int r    = idx & 1;
    int lane = (idx >> 1) & 31;
    int g8   = idx >> 6;
    int NT8  = N / 8;
    int k16  = g8 / NT8;
    int n8   = g8 % NT8;
    int k = k16 * 16 + (lane & 3) * 2 + r * 8;
    int n = n8 * 8 + (lane >> 2);
    int col = ileaveD ? (n & 3) * ileaveD + (n >> 2) : n;
    float e0 = W[(size_t)k * N + col];
    float e1 = W[(size_t)(k + 1) * N + col];
    __nv_bfloat162 p = __floats2bfloat162_rn(e0, e1);
    pa.dst[s][idx] = *(unsigned*)&p;
}

// -------- bf16 tensor-core fused GEMM (2 CTAs/SM — verified R14 win) ---------
__global__ void __launch_bounds__(256, 2) gemm_tc(
    const float* __restrict__ A0, int K0, const unsigned* __restrict__ Bp0,
    const float* __restrict__ A1, int K1, const unsigned* __restrict__ Bp1,
    const float* __restrict__ bias0, const float* __restrict__ bias1,
    float* __restrict__ Cf, unsigned* __restrict__ Cb,
    int Ntot, int act_sigmoid, int ileaveD)
{
    __shared__ __nv_bfloat16 As[128 * 136];

    const int tid  = threadIdx.x;
    const int lane = tid & 31;
    const int warp = tid >> 5;
    const int m0   = blockIdx.x * 128;
    const int nb0  = blockIdx.y * 16;      // n8 base
    const int NT8  = Ntot / 8;

    float acc[16][4];
#pragma unroll
    for (int nt = 0; nt < 16; nt++)
#pragma unroll
        for (int q = 0; q < 4; q++) acc[nt][q] = 0.0f;

    for (int pair = 0; pair < 2; pair++) {
        const float* A = pair ? A1 : A0;
        const unsigned* Bp = pair ? Bp1 : Bp0;
        const int K = pair ? K1 : K0;
        if (A == nullptr || K == 0) continue;
        const int KP = K + 8;
        const int K16 = K / 16;
        const int KC = K / 4;

        __syncthreads();
        for (int i = tid; i < 128 * KC; i += 256) {
            int row = i / KC, cc = i % KC;
            float4 v = *(const float4*)(A + (size_t)(m0 + row) * K + cc * 4);
            __nv_bfloat162 lo = __floats2bfloat162_rn(v.x, v.y);
            __nv_bfloat162 hi = __floats2bfloat162_rn(v.z, v.w);
            uint2 u = {*(unsigned*)&lo, *(unsigned*)&hi};
            *(uint2*)&As[row * KP + cc * 4] = u;
        }
        __syncthreads();

        const int arow  = warp * 16 + (lane & 15);
        const int acolb = (lane >> 4) << 3;
        for (int k16 = 0; k16 < K16; k16++) {
            unsigned a0, a1, a2, a3;
            unsigned addr =
                (unsigned)__cvta_generic_to_shared(&As[arow * KP + k16 * 16 + acolb]);
            asm volatile(
                "ldmatrix.sync.aligned.m8n8.x4.shared.b16 {%0,%1,%2,%3}, [%4];"
                : "=r"(a0), "=r"(a1), "=r"(a2), "=r"(a3) : "r"(addr));
#pragma unroll
            for (int nt = 0; nt < 16; nt++) {
                uint2 b = ((const uint2*)Bp)[(k16 * NT8 + nb0 + nt) * 32 + lane];
                asm volatile(
                    "mma.sync.aligned.m16n8k16.row.col.f32.bf16.bf16.f32 "
                    "{%0,%1,%2,%3},{%4,%5,%6,%7},{%8,%9},{%0,%1,%2,%3};"
                    : "+f"(acc[nt][0]), "+f"(acc[nt][1]), "+f"(acc[nt][2]), "+f"(acc[nt][3])
                    : "r"(a0), "r"(a1), "r"(a2), "r"(a3), "r"(b.x), "r"(b.y));
            }
        }
    }

    // epilogue
    const int r0 = m0 + warp * 16 + (lane >> 2);
    const int r1 = r0 + 8;
#pragma unroll
    for (int nt = 0; nt < 16; nt++) {
        int ci = (nb0 + nt) * 8 + 2 * (lane & 3);
        int lgA = ileaveD ? (ci & 3) * ileaveD + (ci >> 2) : ci;
        int cj = ci + 1;
        int lgB = ileaveD ? (cj & 3) * ileaveD + (cj >> 2) : cj;
        float bA = (bias0 ? bias0[lgA] : 0.0f) + (bias1 ? bias1[lgA] : 0.0f);
        float bB = (bias0 ? bias0[lgB] : 0.0f) + (bias1 ? bias1[lgB] : 0.0f);
        float v00 = acc[nt][0] + bA, v01 = acc[nt][1] + bB;
        float v10 = acc[nt][2] + bA, v11 = acc[nt][3] + bB;
        if (act_sigmoid) {
            v00 = 1.0f / (1.0f + __expf(-v00));
            v01 = 1.0f / (1.0f + __expf(-v01));
            v10 = 1.0f / (1.0f + __expf(-v10));
            v11 = 1.0f / (1.0f + __expf(-v11));
        }
        if (Cb) {
            __nv_bfloat162 p0 = __floats2bfloat162_rn(v00, v01);
            __nv_bfloat162 p1 = __floats2bfloat162_rn(v10, v11);
            Cb[(size_t)r0 * (Ntot / 2) + (ci >> 1)] = *(unsigned*)&p0;
            Cb[(size_t)r1 * (Ntot / 2) + (ci >> 1)] = *(unsigned*)&p1;
        } else {
            float2 f0 = {v00, v01}, f1 = {v10, v11};
            *(float2*)&Cf[(size_t)r0 * Ntot + ci] = f0;
            *(float2*)&Cf[(size_t)r1 * Ntot + ci] = f1;
        }
    }
}

// -------- persistent bf16 tensor-core LSTM (exact Round-8 structure) ---------
// One CTA = 32 nodes. h double-buffered in smem (bf16); c in registers; full
// packed Whh in smem. Per step: gather P[nbr] (independent of h) BEFORE the
// barrier so its L2 latency overlaps the barrier wait; then mma; then epilogue
// writing the other h buffer. ONE syncthreads per step. No cross-step
// prefetch: layer1's 2-CTA/SM config caps registers at 64/thread and any
// extra live state spills (measured R14 regression).
template <int DIM, int WN, int NTHREADS, int MINCTA>
__global__ void __launch_bounds__(NTHREADS, MINCTA) lstm_persist(
    const unsigned* __restrict__ Pu,  // [NN][2*DIM] bf16 pairs (4*DIM cols)
    const unsigned* __restrict__ Bpk, // packed bf16 Whh
    const int*      __restrict__ nbr, // [NN][16]
    float*          __restrict__ HN)  // [NN][DIM] final h
{
    constexpr int C4     = 4 * DIM;
    constexpr int C2     = 2 * DIM;
    constexpr int K16    = DIM / 16;
    constexpr int NT8    = C4 / 8;
    constexpr int WC     = C4 / WN;
    constexpr int NTILES = WC / 8;
    constexpr int HP     = DIM + 8;

    extern __shared__ unsigned smem_u[];
    unsigned*       Bsm = smem_u;                                   // DIM*C4/2 uints
    __nv_bfloat16*  Hs0 = (__nv_bfloat16*)(smem_u + DIM * C4 / 2);  // [32][HP]
    __nv_bfloat16*  Hs1 = Hs0 + 32 * HP;

    const int tid  = threadIdx.x;
    const int lane = tid & 31;
    const int warp = tid >> 5;
    const int wm   = warp / WN;     // 0..1 : 16-row slab
    const int wn   = warp % WN;     // 0..WN-1 : WC-col slab
    const int base = blockIdx.x * 32;

    // load packed B into smem (one time; reused all 16 steps)
    for (int i = tid; i < DIM * C4 / 8; i += NTHREADS)
        ((uint4*)Bsm)[i] = ((const uint4*)Bpk)[i];
    __syncthreads();

    float creg[NTILES][2];
#pragma unroll
    for (int nt = 0; nt < NTILES; nt++) { creg[nt][0] = 0.0f; creg[nt][1] = 0.0f; }

    const int  r0 = wm * 16 + (lane >> 2);
    const int  r1 = r0 + 8;
    const bool evenp = ((lane & 1) == 0);
    const int  arow  = wm * 16 + (lane & 15);
    const int  acolb = (lane >> 4) << 3;

    for (int t = 0; t < KK; t++) {
        // ---- gather P (independent of h) BEFORE the barrier ----------------
        const int j0 = __ldg(&nbr[(base + r0) * KK + t]);
        const int j1 = __ldg(&nbr[(base + r1) * KK + t]);
        unsigned pp0[NTILES], pp1[NTILES];
#pragma unroll
        for (int nt = 0; nt < NTILES; nt++) {
            int cu = ((wn * WC + nt * 8) >> 1) + (lane & 3);
            pp0[nt] = __ldg(&Pu[(size_t)j0 * C2 + cu]);
            pp1[nt] = __ldg(&Pu[(size_t)j1 * C2 + cu]);
        }

        __syncthreads();   // h_{t-1} writes (prev epilogue) now visible

        float acc[NTILES][4];
#pragma unroll
        for (int nt = 0; nt < NTILES; nt++)
            acc[nt][0] = acc[nt][1] = acc[nt][2] = acc[nt][3] = 0.0f;

        if (t > 0) {
            const __nv_bfloat16* Hr = (t & 1) ? Hs1 : Hs0;
#pragma unroll
            for (int k16 = 0; k16 < K16; k16++) {
                unsigned a0, a1, a2, a3;
                unsigned addr =
                    (unsigned)__cvta_generic_to_shared(&Hr[arow * HP + k16 * 16 + acolb]);
                asm volatile(
                    "ldmatrix.sync.aligned.m8n8.x4.shared.b16 {%0,%1,%2,%3}, [%4];"
                    : "=r"(a0), "=r"(a1), "=r"(a2), "=r"(a3) : "r"(addr));
#pragma unroll
                for (int nt = 0; nt < NTILES; nt++) {
                    uint2 b = ((const uint2*)Bsm)[(k16 * NT8 + wn * NTILES + nt) * 32 + lane];
                    asm volatile(
                        "mma.sync.aligned.m16n8k16.row.col.f32.bf16.bf16.f32 "
                        "{%0,%1,%2,%3},{%4,%5,%6,%7},{%8,%9},{%0,%1,%2,%3};"
                        : "+f"(acc[nt][0]), "+f"(acc[nt][1]), "+f"(acc[nt][2]), "+f"(acc[nt][3])
                        : "r"(a0), "r"(a1), "r"(a2), "r"(a3), "r"(b.x), "r"(b.y));
                }
            }
        }

        // ---- epilogue: cell update; writes go to the OTHER h buffer --------
        __nv_bfloat16* Hw = (t & 1) ? Hs0 : Hs1;
#pragma unroll
        for (int nt = 0; nt < NTILES; nt++) {
            int ci = wn * WC + nt * 8 + 2 * (lane & 3);
            int d  = ci >> 2;
            float2 p0 = __bfloat1622float2(*(__nv_bfloat162*)&pp0[nt]);
            float2 p1 = __bfloat1622float2(*(__nv_bfloat162*)&pp1[nt]);
            float g00 = acc[nt][0] + p0.x;   // even lane: i | odd lane: g
            float g01 = acc[nt][1] + p0.y;   // even lane: f | odd lane: o
            float g10 = acc[nt][2] + p1.x;
            float g11 = acc[nt][3] + p1.y;
            float x00 = evenp ? sig_fast(g00) : tanh_fast(g00);
            float x01 = sig_fast(g01);
            float x10 = evenp ? sig_fast(g10) : tanh_fast(g10);
            float x11 = sig_fast(g11);
            float y00 = __shfl_xor_sync(0xffffffffu, x00, 1);  // even view: tanh(g)
            float y10 = __shfl_xor_sync(0xffffffffu, x10, 1);
            float cn0 = x01 * creg[nt][0] + x00 * y00;         // even: sf*c + si*tg
            float cn1 = x11 * creg[nt][1] + x10 * y10;
            float tc0 = tanh_fast(cn0);
            float tc1 = tanh_fast(cn1);
            float tz0 = __shfl_xor_sync(0xffffffffu, tc0, 1);  // odd view: tanh(c)
            float tz1 = __shfl_xor_sync(0xffffffffu, tc1, 1);
            if (evenp) {
                creg[nt][0] = cn0;
                creg[nt][1] = cn1;
            } else {
                float h0 = x01 * tz0;                          // so * tanh(c)
                float h1 = x11 * tz1;
                Hw[r0 * HP + d] = __float2bfloat16(h0);
                Hw[r1 * HP + d] = __float2bfloat16(h1);
                if (t == KK - 1) {
                    HN[(size_t)(base + r0) * DIM + d] = h0;
                    HN[(size_t)(base + r1) * DIM + d] = h1;
                }
            }
        }
    }
}

// -------- per-graph readout + 2-layer head -----------------------------------
__global__ void __launch_bounds__(128) readout_kernel(
    const float* __restrict__ H2,
    const float* __restrict__ rwW, const float* __restrict__ rwb,
    const float* __restrict__ h1W, const float* __restrict__ h1b,
    const float* __restrict__ h2W, const float* __restrict__ h2b,
    float* __restrict__ out)
{
    const int g = blockIdx.x;
    const int t = threadIdx.x;
    __shared__ float h2s[32][128];
    __shared__ float wv[32];
    __shared__ float gembs[256];
    __shared__ float y1s[128];

    for (int idx = t; idx < 32 * 128; idx += 128)
        h2s[idx >> 7][idx & 127] = H2[(size_t)g * 32 * 128 + idx];
    __syncthreads();

    const int warp = t >> 5, lane = t & 31;
    float r0 = rwW[lane], r1 = rwW[lane + 32], r2 = rwW[lane + 64], r3 = rwW[lane + 96];
    for (int mm = 0; mm < 8; mm++) {
        int m = warp * 8 + mm;
        float s = h2s[m][lane] * r0 + h2s[m][lane + 32] * r1
                + h2s[m][lane + 64] * r2 + h2s[m][lane + 96] * r3;
#pragma unroll
        for (int o = 16; o; o >>= 1) s += __shfl_down_sync(0xffffffffu, s, o);
        if (lane == 0) wv[m] = 1.0f / (1.0f + __expf(-(s + rwb[0])));
    }
    __syncthreads();

    {
        float ws = 0.0f, mx = -INFINITY;
#pragma unroll
        for (int m = 0; m < 32; m++) {
            float v = h2s[m][t];
            ws += wv[m] * v;
            mx = fmaxf(mx, v);
        }
        gembs[t] = ws;
        gembs[128 + t] = mx;
    }
    __syncthreads();

    {
        float s = h1b[t];
        for (int cc = 0; cc < 256; cc++) s += gembs[cc] * h1W[cc * 128 + t];
        y1s[t] = 1.0f / (1.0f + __expf(-s));
    }
    __syncthreads();

    if (t < 2) {
        float s = h2b[t];
        for (int j = 0; j < 128; j++) s += y1s[j] * h2W[j * 2 + t];
        out[g * 2 + t] = 1.0f / (1.0f + __expf(-s));
    }
}

// ---------------------------- launch -----------------------------------------
extern "C" void kernel_launch(void* const* d_in, const int* in_sizes, int n_in,
                              void* d_out, int out_size)
{
    const float* xn    = (const float*)d_in[0];
    const int*   nbr   = (const int*)  d_in[1];
    const float* l1Wih = (const float*)d_in[4];
    const float* l1Whh = (const float*)d_in[5];
    const float* l1b   = (const float*)d_in[6];
    const float* fs1W  = (const float*)d_in[7];
    const float* fs1b  = (const float*)d_in[8];
    const float* fn1W  = (const float*)d_in[9];
    const float* fn1b  = (const float*)d_in[10];
    const float* l2Wih = (const float*)d_in[11];
    const float* l2Whh = (const float*)d_in[12];
    const float* l2b   = (const float*)d_in[13];
    const float* fs2W  = (const float*)d_in[14];
    const float* fs2b  = (const float*)d_in[15];
    const float* fn2W  = (const float*)d_in[16];
    const float* fn2b  = (const float*)d_in[17];
    const float* rwW   = (const float*)d_in[18];
    const float* rwb   = (const float*)d_in[19];
    const float* h1W   = (const float*)d_in[20];
    const float* h1b   = (const float*)d_in[21];
    const float* h2W   = (const float*)d_in[22];
    const float* h2b   = (const float*)d_in[23];
    float* out = (float*)d_out;

    unsigned *Pu1, *Pu2, *Wih1, *Wfs1, *Wfn1, *Whh1, *Wih2, *Wfs2, *Wfn2, *Whh2;
    float *HN1, *H1, *HN2, *H2;
    cudaGetSymbolAddress((void**)&Pu1,  g_Pu1);
    cudaGetSymbolAddress((void**)&Pu2,  g_Pu2);
    cudaGetSymbolAddress((void**)&HN1,  g_HN1);
    cudaGetSymbolAddress((void**)&H1,   g_H1);
    cudaGetSymbolAddress((void**)&HN2,  g_HN2);
    cudaGetSymbolAddress((void**)&H2,   g_H2);
    cudaGetSymbolAddress((void**)&Wih1, g_Wih1);
    cudaGetSymbolAddress((void**)&Wfs1, g_Wfs1);
    cudaGetSymbolAddress((void**)&Wfn1, g_Wfn1);
    cudaGetSymbolAddress((void**)&Whh1, g_Whh1);
    cudaGetSymbolAddress((void**)&Wih2, g_Wih2);
    cudaGetSymbolAddress((void**)&Wfs2, g_Wfs2);
    cudaGetSymbolAddress((void**)&Wfn2, g_Wfn2);
    cudaGetSymbolAddress((void**)&Whh2, g_Whh2);

    // smem: packed Whh + double-buffered h [2][32][DIM+8] bf16  (Round-8 geom)
    const int smem1 = 64 * 256 * 2 + 2 * 32 * (64 + 8) * 2;     //  41984 B
    const int smem2 = 128 * 512 * 2 + 2 * 32 * (128 + 8) * 2;   // 148480 B
    cudaFuncSetAttribute((const void*)lstm_persist<64, 8, 512, 2>,
                         cudaFuncAttributeMaxDynamicSharedMemorySize, smem1);
    cudaFuncSetAttribute((const void*)lstm_persist<128, 16, 1024, 1>,
                         cudaFuncAttributeMaxDynamicSharedMemorySize, smem2);

    // ---- pack all weights in ONE launch ------------------------------------
    PackArgs pa;
    pa.src[0] = l1Wih; pa.dst[0] = Wih1;
    pa.src[1] = fs1W;  pa.dst[1] = Wfs1;
    pa.src[2] = fn1W;  pa.dst[2] = Wfn1;
    pa.src[3] = l1Whh; pa.dst[3] = Whh1;
    pa.src[4] = l2Wih; pa.dst[4] = Wih2;
    pa.src[5] = fs2W;  pa.dst[5] = Wfs2;
    pa.src[6] = fn2W;  pa.dst[6] = Wfn2;
    pa.src[7] = l2Whh; pa.dst[7] = Whh2;
    pack_all<<<(106496 + 255) / 256, 256>>>(pa);

    // P1 = x @ Wih1 + b1  (gate-interleaved, bf16 pairs)
    gemm_tc<<<dim3(NN / 128, 2), 256>>>(
        xn, 64, Wih1, nullptr, 0, nullptr, l1b, nullptr,
        nullptr, Pu1, 256, 0, 64);

    // layer1 LSTM (512 threads, 2 CTAs/SM — exact Round-8 config)
    lstm_persist<64, 8, 512, 2><<<NN / 32, 512, smem1>>>(Pu1, Whh1, nbr, HN1);

    // H1 = sigmoid(x@Ws1 + HN1@Wn1 + bs1 + bn1)
    gemm_tc<<<dim3(NN / 128, 1), 256>>>(
        xn, 64, Wfs1, HN1, 64, Wfn1, fs1b, fn1b,
        H1, nullptr, 128, 1, 0);

    // P2 = H1 @ Wih2 + b2  (gate-interleaved, bf16 pairs)
    gemm_tc<<<dim3(NN / 128, 4), 256>>>(
        H1, 128, Wih2, nullptr, 0, nullptr, l2b, nullptr,
        nullptr, Pu2, 512, 0, 128);

    // layer2 LSTM (1024 threads = 32 warps — exact Round-8 config)
    lstm_persist<128, 16, 1024, 1><<<NN / 32, 1024, smem2>>>(Pu2, Whh2, nbr, HN2);

    // H2 = sigmoid(H1@Ws2 + HN2@Wn2 + bs2 + bn2)
    gemm_tc<<<dim3(NN / 128, 1), 256>>>(
        H1, 128, Wfs2, HN2, 128, Wfn2, fs2b, fn2b,
        H2, nullptr, 128, 1, 0);

    // readout + head
    readout_kernel<<<1024, 128>>>(H2, rwW, rwb, h1W, h1b, h2W, h2b, out);
}